// round 2
// baseline (speedup 1.0000x reference)
#include <cuda_runtime.h>
#include <cuda_bf16.h>
#include <math.h>

#define B_DIM   2
#define S_LEN   4096
#define HID     640
#define NH      4
#define HD      256
#define WIN     512
#define NQ      (NH * HD)          // 1024
#define MROWS   (B_DIM * S_LEN)    // 8192
#define SCALING 0.0625f            // 256^-0.5
#define SOFTCAP 50.0f
#define EPS_RMS 1e-6f
#define QT      64
#define KT      64

// ---------------------------------------------------------------------------
// Scratch (static device globals: allocation-free rule)
// ---------------------------------------------------------------------------
__device__ float g_Qraw[(size_t)MROWS * NQ];   // QKV gemm out; later reused as attn output
__device__ float g_Kraw[(size_t)MROWS * HD];
__device__ float g_Vraw[(size_t)MROWS * HD];
__device__ float g_Qr[(size_t)MROWS * NQ];     // [B][NH][S][HD], normed+roped, pre-scaled
__device__ float g_Kr[(size_t)MROWS * HD];     // [B][S][HD], normed+roped

// ---------------------------------------------------------------------------
// SGEMM: C[M,N] = A[M,K] @ B[K,N], all row-major fp32.
// 128x128 block tile, BK=16, 256 threads, 8x8 thread tile, float4 everywhere.
// Requires M%128==0, N%128==0, K%16==0 (true for all 4 calls).
// ---------------------------------------------------------------------------
__global__ void __launch_bounds__(256) sgemm128(
    const float* __restrict__ A, const float* __restrict__ B,
    float* __restrict__ C, int M, int N, int K)
{
    __shared__ float As[16][132];   // transposed A tile [k][m], padded
    __shared__ float Bs[16][128];

    const int bm = blockIdx.y * 128;
    const int bn = blockIdx.x * 128;
    const int t  = threadIdx.x;
    const int ty = t >> 4, tx = t & 15;

    float acc[8][8];
#pragma unroll
    for (int i = 0; i < 8; i++)
#pragma unroll
        for (int j = 0; j < 8; j++) acc[i][j] = 0.f;

    const int ar = t >> 2;          // 0..63
    const int ak = (t & 3) << 2;    // 0,4,8,12
    const int br = t >> 5;          // 0..7
    const int bc = (t & 31) << 2;   // 0..124

    for (int k0 = 0; k0 < K; k0 += 16) {
        float4 a0 = *(const float4*)(A + (size_t)(bm + ar) * K + k0 + ak);
        float4 a1 = *(const float4*)(A + (size_t)(bm + ar + 64) * K + k0 + ak);
        As[ak + 0][ar] = a0.x; As[ak + 1][ar] = a0.y;
        As[ak + 2][ar] = a0.z; As[ak + 3][ar] = a0.w;
        As[ak + 0][ar + 64] = a1.x; As[ak + 1][ar + 64] = a1.y;
        As[ak + 2][ar + 64] = a1.z; As[ak + 3][ar + 64] = a1.w;
        *(float4*)(&Bs[br][bc])     = *(const float4*)(B + (size_t)(k0 + br) * N + bn + bc);
        *(float4*)(&Bs[br + 8][bc]) = *(const float4*)(B + (size_t)(k0 + br + 8) * N + bn + bc);
        __syncthreads();

#pragma unroll
        for (int k = 0; k < 16; k++) {
            float a[8], b[8];
            *(float4*)&a[0] = *(const float4*)&As[k][8 * ty];
            *(float4*)&a[4] = *(const float4*)&As[k][8 * ty + 4];
            *(float4*)&b[0] = *(const float4*)&Bs[k][8 * tx];
            *(float4*)&b[4] = *(const float4*)&Bs[k][8 * tx + 4];
#pragma unroll
            for (int i = 0; i < 8; i++)
#pragma unroll
                for (int j = 0; j < 8; j++)
                    acc[i][j] = fmaf(a[i], b[j], acc[i][j]);
        }
        __syncthreads();
    }

#pragma unroll
    for (int i = 0; i < 8; i++) {
        float* Cp = C + (size_t)(bm + 8 * ty + i) * N + bn + 8 * tx;
        *(float4*)(Cp)     = make_float4(acc[i][0], acc[i][1], acc[i][2], acc[i][3]);
        *(float4*)(Cp + 4) = make_float4(acc[i][4], acc[i][5], acc[i][6], acc[i][7]);
    }
}

// ---------------------------------------------------------------------------
// RMSNorm + RoPE for Q (4 heads, pre-scaled by SCALING) and K (1 head).
// One block per (b,s); 256 threads = one element of the 256-dim head each.
// Q out layout: [B][NH][S][HD] (head-major for attention); K out: [B][S][HD].
// ---------------------------------------------------------------------------
__global__ void __launch_bounds__(256) normrope_kernel(
    const float* __restrict__ Qraw, const float* __restrict__ Kraw,
    const float* __restrict__ cosb, const float* __restrict__ sinb,
    const float* __restrict__ qw,   const float* __restrict__ kw,
    float* __restrict__ Qo, float* __restrict__ Ko)
{
    __shared__ float xbuf[HD];
    __shared__ float red[8];

    const int bs   = blockIdx.x;
    const int b    = bs / S_LEN;
    const int sIdx = bs % S_LEN;
    const int t    = threadIdx.x;
    const int lane = t & 31, warp = t >> 5;

    const float c   = cosb[(size_t)sIdx * HD + t];
    const float sn  = sinb[(size_t)sIdx * HD + t];
    const float qwv = 1.0f + qw[t];
    const float kwv = 1.0f + kw[t];

#pragma unroll
    for (int h = 0; h < NH + 1; h++) {
        float x = (h < NH) ? Qraw[(size_t)bs * NQ + h * HD + t]
                           : Kraw[(size_t)bs * HD + t];
        float ss = x * x;
#pragma unroll
        for (int o = 16; o > 0; o >>= 1) ss += __shfl_xor_sync(0xffffffffu, ss, o);
        if (lane == 0) red[warp] = ss;
        __syncthreads();
        float tot = 0.f;
#pragma unroll
        for (int w = 0; w < 8; w++) tot += red[w];
        float inv = rsqrtf(tot * (1.0f / HD) + EPS_RMS);
        float xn  = x * inv * ((h < NH) ? qwv : kwv);
        xbuf[t] = xn;
        __syncthreads();
        float other = (t < 128) ? xbuf[t + 128] : xbuf[t - 128];
        float rot   = (t < 128) ? (xn * c - other * sn) : (xn * c + other * sn);
        if (h < NH) Qo[(((size_t)b * NH + h) * S_LEN + sIdx) * HD + t] = rot * SCALING;
        else        Ko[((size_t)b * S_LEN + sIdx) * HD + t]            = rot;
        __syncthreads();
    }
}

// ---------------------------------------------------------------------------
// Flash-style windowed attention with softcap.
// Block = (q-tile of 64, head, batch). 256 threads.
// Smem: Q^T[256][68], K^T[256][68], V[64][260], P[64][65]  (~217 KB).
// Scores: 16x16 thread grid, 4x4 per-thread tile. Online softmax with
// per-row (m,l) replicated across the 16 lanes owning each row.
// ---------------------------------------------------------------------------
#define QPAD 68
#define VPAD 260
#define PPAD 65
#define ATTN_SMEM_FLOATS (HD * QPAD * 2 + KT * VPAD + QT * PPAD)
#define ATTN_SMEM_BYTES  (ATTN_SMEM_FLOATS * 4)

__global__ void __launch_bounds__(256, 1) attn_kernel(
    const float* __restrict__ Q,   // [B][NH][S][HD], pre-scaled by SCALING
    const float* __restrict__ Kr,  // [B][S][HD]
    const float* __restrict__ V,   // [B*S][HD]
    float* __restrict__ O)         // [B*S][NH*HD]
{
    const int qb = blockIdx.x;
    const int h  = blockIdx.y;
    const int b  = blockIdx.z;
    const int q0 = qb * QT;

    extern __shared__ float sm[];
    float* Qst = sm;                       // [HD][QPAD]
    float* Kst = Qst + HD * QPAD;          // [HD][QPAD]
    float* Vs  = Kst + HD * QPAD;          // [KT][VPAD]
    float* Ps  = Vs + KT * VPAD;           // [QT][PPAD]

    const int t  = threadIdx.x;
    const int ty = t >> 4, tx = t & 15;

    // ---- load Q tile transposed: Qst[d][q] ----
    {
        const float* Qg = Q + (((size_t)b * NH + h) * S_LEN + q0) * HD;
        const int r  = t >> 2;            // q row
        const int cc = (t & 3) << 2;      // base d
#pragma unroll
        for (int i = 0; i < 16; i++) {
            int d = cc + i * 16;
            float4 v4 = *(const float4*)(Qg + (size_t)r * HD + d);
            Qst[(d + 0) * QPAD + r] = v4.x;
            Qst[(d + 1) * QPAD + r] = v4.y;
            Qst[(d + 2) * QPAD + r] = v4.z;
            Qst[(d + 3) * QPAD + r] = v4.w;
        }
    }

    float m_r[4], l_r[4];
    float o_acc[4][16];
#pragma unroll
    for (int r = 0; r < 4; r++) {
        m_r[r] = -1e30f; l_r[r] = 0.f;
#pragma unroll
        for (int c = 0; c < 16; c++) o_acc[r][c] = 0.f;
    }

    const int kt_lo = (qb >= 8) ? (qb - 8) : 0;
    for (int kt = kt_lo; kt <= qb; kt++) {
        const int j0 = kt * KT;
        __syncthreads();   // prev PV done reading Ps/Vs
        // ---- load K tile transposed + V tile ----
        {
            const float* Kg = Kr + ((size_t)b * S_LEN + j0) * HD;
            const float* Vg = V + ((size_t)b * S_LEN + j0) * HD;
            const int r  = t >> 2;
            const int cc = (t & 3) << 2;
#pragma unroll
            for (int i = 0; i < 16; i++) {
                int d = cc + i * 16;
                float4 kv = *(const float4*)(Kg + (size_t)r * HD + d);
                Kst[(d + 0) * QPAD + r] = kv.x;
                Kst[(d + 1) * QPAD + r] = kv.y;
                Kst[(d + 2) * QPAD + r] = kv.z;
                Kst[(d + 3) * QPAD + r] = kv.w;
                *(float4*)(Vs + (size_t)r * VPAD + d) = *(const float4*)(Vg + (size_t)r * HD + d);
            }
        }
        __syncthreads();

        // ---- scores: S = Qtile @ Ktile^T  (4x4 per thread) ----
        float s[4][4];
#pragma unroll
        for (int r = 0; r < 4; r++)
#pragma unroll
            for (int c = 0; c < 4; c++) s[r][c] = 0.f;

#pragma unroll 8
        for (int d = 0; d < HD; d++) {
            float4 a  = *(const float4*)(Qst + d * QPAD + 4 * ty);
            float4 bb = *(const float4*)(Kst + d * QPAD + 4 * tx);
            s[0][0] = fmaf(a.x, bb.x, s[0][0]); s[0][1] = fmaf(a.x, bb.y, s[0][1]);
            s[0][2] = fmaf(a.x, bb.z, s[0][2]); s[0][3] = fmaf(a.x, bb.w, s[0][3]);
            s[1][0] = fmaf(a.y, bb.x, s[1][0]); s[1][1] = fmaf(a.y, bb.y, s[1][1]);
            s[1][2] = fmaf(a.y, bb.z, s[1][2]); s[1][3] = fmaf(a.y, bb.w, s[1][3]);
            s[2][0] = fmaf(a.z, bb.x, s[2][0]); s[2][1] = fmaf(a.z, bb.y, s[2][1]);
            s[2][2] = fmaf(a.z, bb.z, s[2][2]); s[2][3] = fmaf(a.z, bb.w, s[2][3]);
            s[3][0] = fmaf(a.w, bb.x, s[3][0]); s[3][1] = fmaf(a.w, bb.y, s[3][1]);
            s[3][2] = fmaf(a.w, bb.z, s[3][2]); s[3][3] = fmaf(a.w, bb.w, s[3][3]);
        }

        // ---- softcap + window mask + online softmax ----
#pragma unroll
        for (int r = 0; r < 4; r++) {
            const int q = q0 + 4 * ty + r;
            float mt = -1e30f;
#pragma unroll
            for (int c = 0; c < 4; c++) {
                const int j = j0 + 4 * tx + c;
                const bool ok = (j <= q) && (j > q - WIN);
                float x = s[r][c];
                // 50*tanh(x/50) = 50*(1 - 2/(exp(2x/50)+1))
                float e  = __expf(x * (2.0f / SOFTCAP));
                float sc = SOFTCAP * (1.0f - __fdividef(2.0f, e + 1.0f));
                s[r][c] = ok ? sc : -1e30f;
                mt = fmaxf(mt, s[r][c]);
            }
#pragma unroll
            for (int w = 1; w < 16; w <<= 1)
                mt = fmaxf(mt, __shfl_xor_sync(0xffffffffu, mt, w));
            float newm = fmaxf(m_r[r], mt);
            float f    = __expf(m_r[r] - newm);
            m_r[r] = newm;
            float rs = 0.f;
#pragma unroll
            for (int c = 0; c < 4; c++) {
                float p = (s[r][c] > -1e29f) ? __expf(s[r][c] - newm) : 0.f;
                Ps[(4 * ty + r) * PPAD + 4 * tx + c] = p;
                rs += p;
            }
#pragma unroll
            for (int w = 1; w < 16; w <<= 1)
                rs += __shfl_xor_sync(0xffffffffu, rs, w);
            l_r[r] = l_r[r] * f + rs;
#pragma unroll
            for (int c = 0; c < 16; c++) o_acc[r][c] *= f;
        }
        __syncthreads();   // Ps visible to all

        // ---- O += P @ Vtile ----
#pragma unroll 2
        for (int j = 0; j < KT; j++) {
            float p0 = Ps[(4 * ty + 0) * PPAD + j];
            float p1 = Ps[(4 * ty + 1) * PPAD + j];
            float p2 = Ps[(4 * ty + 2) * PPAD + j];
            float p3 = Ps[(4 * ty + 3) * PPAD + j];
#pragma unroll
            for (int c = 0; c < 16; c++) {
                float v = Vs[j * VPAD + c * 16 + tx];
                o_acc[0][c] = fmaf(p0, v, o_acc[0][c]);
                o_acc[1][c] = fmaf(p1, v, o_acc[1][c]);
                o_acc[2][c] = fmaf(p2, v, o_acc[2][c]);
                o_acc[3][c] = fmaf(p3, v, o_acc[3][c]);
            }
        }
    }

    // ---- epilogue: normalize, write [b*S+q][h*HD + d] ----
#pragma unroll
    for (int r = 0; r < 4; r++) {
        const int q = q0 + 4 * ty + r;
        float inv = __fdividef(1.0f, l_r[r]);
        float* Og = O + ((size_t)b * S_LEN + q) * NQ + h * HD;
#pragma unroll
        for (int c = 0; c < 16; c++) Og[c * 16 + tx] = o_acc[r][c] * inv;
    }
}

// ---------------------------------------------------------------------------
// Launch
// ---------------------------------------------------------------------------
extern "C" void kernel_launch(void* const* d_in, const int* in_sizes, int n_in,
                              void* d_out, int out_size)
{
    (void)in_sizes; (void)n_in; (void)out_size;
    const float* hidden = (const float*)d_in[0];
    const float* cosb   = (const float*)d_in[1];
    const float* sinb   = (const float*)d_in[2];
    // d_in[3] = attention_mask: analytic sliding-window mask used instead
    const float* Wq = (const float*)d_in[4];
    const float* Wk = (const float*)d_in[5];
    const float* Wv = (const float*)d_in[6];
    const float* Wo = (const float*)d_in[7];
    const float* qw = (const float*)d_in[8];
    const float* kw = (const float*)d_in[9];
    float* out = (float*)d_out;

    float *qraw, *kraw, *vraw, *qr, *kr;
    cudaGetSymbolAddress((void**)&qraw, g_Qraw);
    cudaGetSymbolAddress((void**)&kraw, g_Kraw);
    cudaGetSymbolAddress((void**)&vraw, g_Vraw);
    cudaGetSymbolAddress((void**)&qr, g_Qr);
    cudaGetSymbolAddress((void**)&kr, g_Kr);

    // QKV projections
    sgemm128<<<dim3(NQ / 128, MROWS / 128), 256>>>(hidden, Wq, qraw, MROWS, NQ, HID);
    sgemm128<<<dim3(HD / 128, MROWS / 128), 256>>>(hidden, Wk, kraw, MROWS, HD, HID);
    sgemm128<<<dim3(HD / 128, MROWS / 128), 256>>>(hidden, Wv, vraw, MROWS, HD, HID);

    // RMSNorm + RoPE (Q pre-scaled by SCALING)
    normrope_kernel<<<MROWS, 256>>>(qraw, kraw, cosb, sinb, qw, kw, qr, kr);

    // Windowed softcap attention (writes into qraw, reused as scratch)
    cudaFuncSetAttribute(attn_kernel, cudaFuncAttributeMaxDynamicSharedMemorySize,
                         ATTN_SMEM_BYTES);
    attn_kernel<<<dim3(S_LEN / QT, NH, B_DIM), 256, ATTN_SMEM_BYTES>>>(qr, kr, vraw, qraw);

    // Output projection
    sgemm128<<<dim3(HID / 128, MROWS / 128), 256>>>(qraw, Wo, out, MROWS, HID, NQ);
}

// round 4
// speedup vs baseline: 1.5559x; 1.5559x over previous
#include <cuda_runtime.h>
#include <cuda_bf16.h>
#include <stdint.h>
#include <math.h>

#define B_DIM   2
#define S_LEN   4096
#define HID     640
#define NH      4
#define HD      256
#define WIN     512
#define NQ      (NH * HD)          // 1024
#define MROWS   (B_DIM * S_LEN)    // 8192
#define SCALING 0.0625f            // 256^-0.5
#define SOFTCAP 50.0f
#define EPS_RMS 1e-6f
#define QT      64
#define KT      64

// ---------------------------------------------------------------------------
// Scratch (static device globals: allocation-free rule)
// ---------------------------------------------------------------------------
__device__ float g_Qraw[(size_t)MROWS * NQ];   // QKV gemm out; later reused as attn output
__device__ float g_Kraw[(size_t)MROWS * HD];
__device__ float g_Vraw[(size_t)MROWS * HD];
__device__ float g_Qr[(size_t)MROWS * NQ];     // [B][NH][S][HD], normed+roped, pre-scaled
__device__ float g_Kr[(size_t)MROWS * HD];     // [B][S][HD], normed+roped

// ===========================================================================
// TF32 tensor-core GEMM: C[M,N] = A[M,K] @ B[K,N], fp32 in/out, tf32 mma.
// 128x128x16 block tile, 256 threads (8 warps), warp tile 64x32,
// mma.sync.aligned.m16n8k8 (4 m-tiles x 4 n-tiles per warp per k-step).
// A tile stored transposed [k][m] with XOR swizzle -> conflict-free LDS+STS.
// Double-buffered smem + register prefetch of the next tile.
// ===========================================================================
#define GSTRIDE 136                    // 136 mod 32 == 8
#define GBUF    (16 * GSTRIDE)         // 2176 words per buffer
// swizzle: XOR bits [3:4] of m with (k>>2)
#define ASW(k, m) ((k) * GSTRIDE + ((m) ^ ((((k) >> 2) & 3) << 3)))

typedef unsigned int u32;

__device__ __forceinline__ u32 f2tf32(float x) {
    u32 r;
    asm("cvt.rna.tf32.f32 %0, %1;" : "=r"(r) : "f"(x));
    return r;
}

__device__ __forceinline__ void mma_tf32(float* c,
    u32 a0, u32 a1, u32 a2, u32 a3, u32 b0, u32 b1)
{
    asm volatile(
        "mma.sync.aligned.m16n8k8.row.col.f32.tf32.tf32.f32 "
        "{%0,%1,%2,%3}, {%4,%5,%6,%7}, {%8,%9}, {%0,%1,%2,%3};"
        : "+f"(c[0]), "+f"(c[1]), "+f"(c[2]), "+f"(c[3])
        : "r"(a0), "r"(a1), "r"(a2), "r"(a3), "r"(b0), "r"(b1));
}

__device__ __forceinline__ void gemm_body(
    const float* __restrict__ A, const float* __restrict__ Bm,
    float* __restrict__ C, int N, int K, int bm, int bn,
    u32* As, u32* Bs)
{
    const int t    = threadIdx.x;
    const int warp = t >> 5, lane = t & 31;
    const int g    = lane >> 2, tc = lane & 3;
    const int wm   = (warp & 1) * 64;
    const int wn   = (warp >> 1) * 32;

    const int ar = t >> 2;            // A load row within tile (0..63)
    const int ak = (t & 3) << 2;      // A load k base (0,4,8,12)
    const int br = t >> 4;            // B load k row (0..15)
    const int bc = (t & 15) << 2;     // B load col base (0..60)

    float acc[4][4][4];
#pragma unroll
    for (int i = 0; i < 4; i++)
#pragma unroll
        for (int j = 0; j < 4; j++)
#pragma unroll
            for (int r = 0; r < 4; r++) acc[i][j][r] = 0.f;

    const int ktiles = K >> 4;

    float4 a0, a1, b0, b1;
    // ---- prologue: load + store tile 0 ----
    {
        const float* Ap = A + (size_t)(bm + ar) * K + ak;
        a0 = *(const float4*)Ap;
        a1 = *(const float4*)(Ap + (size_t)64 * K);
        const float* Bp = Bm + (size_t)br * N + bn + bc;
        b0 = *(const float4*)Bp;
        b1 = *(const float4*)(Bp + 64);
        u32* a_s = As;
        a_s[ASW(ak + 0, ar)] = f2tf32(a0.x);
        a_s[ASW(ak + 1, ar)] = f2tf32(a0.y);
        a_s[ASW(ak + 2, ar)] = f2tf32(a0.z);
        a_s[ASW(ak + 3, ar)] = f2tf32(a0.w);
        a_s[ASW(ak + 0, ar + 64)] = f2tf32(a1.x);
        a_s[ASW(ak + 1, ar + 64)] = f2tf32(a1.y);
        a_s[ASW(ak + 2, ar + 64)] = f2tf32(a1.z);
        a_s[ASW(ak + 3, ar + 64)] = f2tf32(a1.w);
        u32* b_s = Bs;
        b_s[br * GSTRIDE + bc + 0]  = f2tf32(b0.x);
        b_s[br * GSTRIDE + bc + 1]  = f2tf32(b0.y);
        b_s[br * GSTRIDE + bc + 2]  = f2tf32(b0.z);
        b_s[br * GSTRIDE + bc + 3]  = f2tf32(b0.w);
        b_s[br * GSTRIDE + bc + 64] = f2tf32(b1.x);
        b_s[br * GSTRIDE + bc + 65] = f2tf32(b1.y);
        b_s[br * GSTRIDE + bc + 66] = f2tf32(b1.z);
        b_s[br * GSTRIDE + bc + 67] = f2tf32(b1.w);
    }
    __syncthreads();

    int buf = 0;
    for (int kt = 0; kt < ktiles; kt++) {
        const bool have = (kt + 1) < ktiles;
        if (have) {
            const int k0 = (kt + 1) << 4;
            const float* Ap = A + (size_t)(bm + ar) * K + k0 + ak;
            a0 = *(const float4*)Ap;
            a1 = *(const float4*)(Ap + (size_t)64 * K);
            const float* Bp = Bm + (size_t)(k0 + br) * N + bn + bc;
            b0 = *(const float4*)Bp;
            b1 = *(const float4*)(Bp + 64);
        }

        // ---- compute from smem[buf] ----
        {
            const u32* a_s = As + buf * GBUF;
            const u32* b_s = Bs + buf * GBUF;
#pragma unroll
            for (int ks = 0; ks < 2; ks++) {
                const int kc0 = ks * 8 + tc;
                const int kc1 = kc0 + 4;
                u32 af[4][4], bf[4][2];
#pragma unroll
                for (int mt = 0; mt < 4; mt++) {
                    const int m = wm + mt * 16 + g;
                    af[mt][0] = a_s[ASW(kc0, m)];
                    af[mt][1] = a_s[ASW(kc0, m + 8)];
                    af[mt][2] = a_s[ASW(kc1, m)];
                    af[mt][3] = a_s[ASW(kc1, m + 8)];
                }
#pragma unroll
                for (int nt = 0; nt < 4; nt++) {
                    const int n = wn + nt * 8 + g;
                    bf[nt][0] = b_s[kc0 * GSTRIDE + n];
                    bf[nt][1] = b_s[kc1 * GSTRIDE + n];
                }
#pragma unroll
                for (int mt = 0; mt < 4; mt++)
#pragma unroll
                    for (int nt = 0; nt < 4; nt++)
                        mma_tf32(acc[mt][nt], af[mt][0], af[mt][1], af[mt][2], af[mt][3],
                                 bf[nt][0], bf[nt][1]);
            }
        }

        if (have) {
            u32* a_s = As + (buf ^ 1) * GBUF;
            a_s[ASW(ak + 0, ar)] = f2tf32(a0.x);
            a_s[ASW(ak + 1, ar)] = f2tf32(a0.y);
            a_s[ASW(ak + 2, ar)] = f2tf32(a0.z);
            a_s[ASW(ak + 3, ar)] = f2tf32(a0.w);
            a_s[ASW(ak + 0, ar + 64)] = f2tf32(a1.x);
            a_s[ASW(ak + 1, ar + 64)] = f2tf32(a1.y);
            a_s[ASW(ak + 2, ar + 64)] = f2tf32(a1.z);
            a_s[ASW(ak + 3, ar + 64)] = f2tf32(a1.w);
            u32* b_s = Bs + (buf ^ 1) * GBUF;
            b_s[br * GSTRIDE + bc + 0]  = f2tf32(b0.x);
            b_s[br * GSTRIDE + bc + 1]  = f2tf32(b0.y);
            b_s[br * GSTRIDE + bc + 2]  = f2tf32(b0.z);
            b_s[br * GSTRIDE + bc + 3]  = f2tf32(b0.w);
            b_s[br * GSTRIDE + bc + 64] = f2tf32(b1.x);
            b_s[br * GSTRIDE + bc + 65] = f2tf32(b1.y);
            b_s[br * GSTRIDE + bc + 66] = f2tf32(b1.z);
            b_s[br * GSTRIDE + bc + 67] = f2tf32(b1.w);
        }
        __syncthreads();
        buf ^= 1;
    }

    // ---- epilogue ----
#pragma unroll
    for (int mt = 0; mt < 4; mt++) {
        const int row0 = bm + wm + mt * 16 + g;
#pragma unroll
        for (int nt = 0; nt < 4; nt++) {
            const int col = bn + wn + nt * 8 + 2 * tc;
            float2 lo = make_float2(acc[mt][nt][0], acc[mt][nt][1]);
            float2 hi = make_float2(acc[mt][nt][2], acc[mt][nt][3]);
            *(float2*)&C[(size_t)row0 * N + col]       = lo;
            *(float2*)&C[(size_t)(row0 + 8) * N + col] = hi;
        }
    }
}

// Fused QKV projection: blockIdx.x 0..7 -> Q tiles, 8..9 -> K, 10..11 -> V.
__global__ void __launch_bounds__(256, 2) gemm_qkv_tf32(
    const float* __restrict__ A,
    const float* __restrict__ Wq, const float* __restrict__ Wk,
    const float* __restrict__ Wv,
    float* __restrict__ Qo, float* __restrict__ Ko, float* __restrict__ Vo)
{
    __shared__ u32 As[2 * GBUF];
    __shared__ u32 Bs[2 * GBUF];
    const int nb = blockIdx.x;
    const float* Bm; float* C; int N, bn;
    if (nb < 8)       { Bm = Wq; C = Qo; N = NQ;  bn = nb * 128; }
    else if (nb < 10) { Bm = Wk; C = Ko; N = HD;  bn = (nb - 8) * 128; }
    else              { Bm = Wv; C = Vo; N = HD;  bn = (nb - 10) * 128; }
    gemm_body(A, Bm, C, N, HID, blockIdx.y * 128, bn, As, Bs);
}

// Plain GEMM (output projection).
__global__ void __launch_bounds__(256, 2) gemm_tf32(
    const float* __restrict__ A, const float* __restrict__ Bm,
    float* __restrict__ C, int N, int K)
{
    __shared__ u32 As[2 * GBUF];
    __shared__ u32 Bs[2 * GBUF];
    gemm_body(A, Bm, C, N, K, blockIdx.y * 128, blockIdx.x * 128, As, Bs);
}

// ---------------------------------------------------------------------------
// RMSNorm + RoPE for Q (4 heads, pre-scaled by SCALING) and K (1 head).
// ---------------------------------------------------------------------------
__global__ void __launch_bounds__(256) normrope_kernel(
    const float* __restrict__ Qraw, const float* __restrict__ Kraw,
    const float* __restrict__ cosb, const float* __restrict__ sinb,
    const float* __restrict__ qw,   const float* __restrict__ kw,
    float* __restrict__ Qo, float* __restrict__ Ko)
{
    __shared__ float xbuf[HD];
    __shared__ float red[8];

    const int bs   = blockIdx.x;
    const int b    = bs / S_LEN;
    const int sIdx = bs % S_LEN;
    const int t    = threadIdx.x;
    const int lane = t & 31, warp = t >> 5;

    const float c   = cosb[(size_t)sIdx * HD + t];
    const float sn  = sinb[(size_t)sIdx * HD + t];
    const float qwv = 1.0f + qw[t];
    const float kwv = 1.0f + kw[t];

#pragma unroll
    for (int h = 0; h < NH + 1; h++) {
        float x = (h < NH) ? Qraw[(size_t)bs * NQ + h * HD + t]
                           : Kraw[(size_t)bs * HD + t];
        float ss = x * x;
#pragma unroll
        for (int o = 16; o > 0; o >>= 1) ss += __shfl_xor_sync(0xffffffffu, ss, o);
        if (lane == 0) red[warp] = ss;
        __syncthreads();
        float tot = 0.f;
#pragma unroll
        for (int w = 0; w < 8; w++) tot += red[w];
        float inv = rsqrtf(tot * (1.0f / HD) + EPS_RMS);
        float xn  = x * inv * ((h < NH) ? qwv : kwv);
        xbuf[t] = xn;
        __syncthreads();
        float other = (t < 128) ? xbuf[t + 128] : xbuf[t - 128];
        float rot   = (t < 128) ? (xn * c - other * sn) : (xn * c + other * sn);
        if (h < NH) Qo[(((size_t)b * NH + h) * S_LEN + sIdx) * HD + t] = rot * SCALING;
        else        Ko[((size_t)b * S_LEN + sIdx) * HD + t]            = rot;
        __syncthreads();
    }
}

// ---------------------------------------------------------------------------
// Flash-style windowed attention with softcap (unchanged this round).
// ---------------------------------------------------------------------------
#define QPAD 68
#define VPAD 260
#define PPAD 65
#define ATTN_SMEM_FLOATS (HD * QPAD * 2 + KT * VPAD + QT * PPAD)
#define ATTN_SMEM_BYTES  (ATTN_SMEM_FLOATS * 4)

__global__ void __launch_bounds__(256, 1) attn_kernel(
    const float* __restrict__ Q,   // [B][NH][S][HD], pre-scaled by SCALING
    const float* __restrict__ Kr,  // [B][S][HD]
    const float* __restrict__ V,   // [B*S][HD]
    float* __restrict__ O)         // [B*S][NH*HD]
{
    const int qb = blockIdx.x;
    const int h  = blockIdx.y;
    const int b  = blockIdx.z;
    const int q0 = qb * QT;

    extern __shared__ float sm[];
    float* Qst = sm;                       // [HD][QPAD]
    float* Kst = Qst + HD * QPAD;          // [HD][QPAD]
    float* Vs  = Kst + HD * QPAD;          // [KT][VPAD]
    float* Ps  = Vs + KT * VPAD;           // [QT][PPAD]

    const int t  = threadIdx.x;
    const int ty = t >> 4, tx = t & 15;

    {
        const float* Qg = Q + (((size_t)b * NH + h) * S_LEN + q0) * HD;
        const int r  = t >> 2;
        const int cc = (t & 3) << 2;
#pragma unroll
        for (int i = 0; i < 16; i++) {
            int d = cc + i * 16;
            float4 v4 = *(const float4*)(Qg + (size_t)r * HD + d);
            Qst[(d + 0) * QPAD + r] = v4.x;
            Qst[(d + 1) * QPAD + r] = v4.y;
            Qst[(d + 2) * QPAD + r] = v4.z;
            Qst[(d + 3) * QPAD + r] = v4.w;
        }
    }

    float m_r[4], l_r[4];
    float o_acc[4][16];
#pragma unroll
    for (int r = 0; r < 4; r++) {
        m_r[r] = -1e30f; l_r[r] = 0.f;
#pragma unroll
        for (int c = 0; c < 16; c++) o_acc[r][c] = 0.f;
    }

    const int kt_lo = (qb >= 8) ? (qb - 8) : 0;
    for (int kt = kt_lo; kt <= qb; kt++) {
        const int j0 = kt * KT;
        __syncthreads();
        {
            const float* Kg = Kr + ((size_t)b * S_LEN + j0) * HD;
            const float* Vg = V + ((size_t)b * S_LEN + j0) * HD;
            const int r  = t >> 2;
            const int cc = (t & 3) << 2;
#pragma unroll
            for (int i = 0; i < 16; i++) {
                int d = cc + i * 16;
                float4 kv = *(const float4*)(Kg + (size_t)r * HD + d);
                Kst[(d + 0) * QPAD + r] = kv.x;
                Kst[(d + 1) * QPAD + r] = kv.y;
                Kst[(d + 2) * QPAD + r] = kv.z;
                Kst[(d + 3) * QPAD + r] = kv.w;
                *(float4*)(Vs + (size_t)r * VPAD + d) = *(const float4*)(Vg + (size_t)r * HD + d);
            }
        }
        __syncthreads();

        float s[4][4];
#pragma unroll
        for (int r = 0; r < 4; r++)
#pragma unroll
            for (int c = 0; c < 4; c++) s[r][c] = 0.f;

#pragma unroll 8
        for (int d = 0; d < HD; d++) {
            float4 a  = *(const float4*)(Qst + d * QPAD + 4 * ty);
            float4 bb = *(const float4*)(Kst + d * QPAD + 4 * tx);
            s[0][0] = fmaf(a.x, bb.x, s[0][0]); s[0][1] = fmaf(a.x, bb.y, s[0][1]);
            s[0][2] = fmaf(a.x, bb.z, s[0][2]); s[0][3] = fmaf(a.x, bb.w, s[0][3]);
            s[1][0] = fmaf(a.y, bb.x, s[1][0]); s[1][1] = fmaf(a.y, bb.y, s[1][1]);
            s[1][2] = fmaf(a.y, bb.z, s[1][2]); s[1][3] = fmaf(a.y, bb.w, s[1][3]);
            s[2][0] = fmaf(a.z, bb.x, s[2][0]); s[2][1] = fmaf(a.z, bb.y, s[2][1]);
            s[2][2] = fmaf(a.z, bb.z, s[2][2]); s[2][3] = fmaf(a.z, bb.w, s[2][3]);
            s[3][0] = fmaf(a.w, bb.x, s[3][0]); s[3][1] = fmaf(a.w, bb.y, s[3][1]);
            s[3][2] = fmaf(a.w, bb.z, s[3][2]); s[3][3] = fmaf(a.w, bb.w, s[3][3]);
        }

#pragma unroll
        for (int r = 0; r < 4; r++) {
            const int q = q0 + 4 * ty + r;
            float mt = -1e30f;
#pragma unroll
            for (int c = 0; c < 4; c++) {
                const int j = j0 + 4 * tx + c;
                const bool ok = (j <= q) && (j > q - WIN);
                float x = s[r][c];
                float e  = __expf(x * (2.0f / SOFTCAP));
                float sc = SOFTCAP * (1.0f - __fdividef(2.0f, e + 1.0f));
                s[r][c] = ok ? sc : -1e30f;
                mt = fmaxf(mt, s[r][c]);
            }
#pragma unroll
            for (int w = 1; w < 16; w <<= 1)
                mt = fmaxf(mt, __shfl_xor_sync(0xffffffffu, mt, w));
            float newm = fmaxf(m_r[r], mt);
            float f    = __expf(m_r[r] - newm);
            m_r[r] = newm;
            float rs = 0.f;
#pragma unroll
            for (int c = 0; c < 4; c++) {
                float p = (s[r][c] > -1e29f) ? __expf(s[r][c] - newm) : 0.f;
                Ps[(4 * ty + r) * PPAD + 4 * tx + c] = p;
                rs += p;
            }
#pragma unroll
            for (int w = 1; w < 16; w <<= 1)
                rs += __shfl_xor_sync(0xffffffffu, rs, w);
            l_r[r] = l_r[r] * f + rs;
#pragma unroll
            for (int c = 0; c < 16; c++) o_acc[r][c] *= f;
        }
        __syncthreads();

#pragma unroll 2
        for (int j = 0; j < KT; j++) {
            float p0 = Ps[(4 * ty + 0) * PPAD + j];
            float p1 = Ps[(4 * ty + 1) * PPAD + j];
            float p2 = Ps[(4 * ty + 2) * PPAD + j];
            float p3 = Ps[(4 * ty + 3) * PPAD + j];
#pragma unroll
            for (int c = 0; c < 16; c++) {
                float v = Vs[j * VPAD + c * 16 + tx];
                o_acc[0][c] = fmaf(p0, v, o_acc[0][c]);
                o_acc[1][c] = fmaf(p1, v, o_acc[1][c]);
                o_acc[2][c] = fmaf(p2, v, o_acc[2][c]);
                o_acc[3][c] = fmaf(p3, v, o_acc[3][c]);
            }
        }
    }

#pragma unroll
    for (int r = 0; r < 4; r++) {
        const int q = q0 + 4 * ty + r;
        float inv = __fdividef(1.0f, l_r[r]);
        float* Og = O + ((size_t)b * S_LEN + q) * NQ + h * HD;
#pragma unroll
        for (int c = 0; c < 16; c++) Og[c * 16 + tx] = o_acc[r][c] * inv;
    }
}

// ---------------------------------------------------------------------------
// Launch
// ---------------------------------------------------------------------------
extern "C" void kernel_launch(void* const* d_in, const int* in_sizes, int n_in,
                              void* d_out, int out_size)
{
    (void)in_sizes; (void)n_in; (void)out_size;
    const float* hidden = (const float*)d_in[0];
    const float* cosb   = (const float*)d_in[1];
    const float* sinb   = (const float*)d_in[2];
    // d_in[3] = attention_mask: analytic sliding-window mask used instead
    const float* Wq = (const float*)d_in[4];
    const float* Wk = (const float*)d_in[5];
    const float* Wv = (const float*)d_in[6];
    const float* Wo = (const float*)d_in[7];
    const float* qw = (const float*)d_in[8];
    const float* kw = (const float*)d_in[9];
    float* out = (float*)d_out;

    float *qraw, *kraw, *vraw, *qr, *kr;
    cudaGetSymbolAddress((void**)&qraw, g_Qraw);
    cudaGetSymbolAddress((void**)&kraw, g_Kraw);
    cudaGetSymbolAddress((void**)&vraw, g_Vraw);
    cudaGetSymbolAddress((void**)&qr, g_Qr);
    cudaGetSymbolAddress((void**)&kr, g_Kr);

    // Fused QKV projection (tf32 tensor cores): 12 n-tiles x 64 m-tiles
    gemm_qkv_tf32<<<dim3(12, MROWS / 128), 256>>>(hidden, Wq, Wk, Wv, qraw, kraw, vraw);

    // RMSNorm + RoPE (Q pre-scaled by SCALING)
    normrope_kernel<<<MROWS, 256>>>(qraw, kraw, cosb, sinb, qw, kw, qr, kr);

    // Windowed softcap attention (writes into qraw, reused as scratch)
    cudaFuncSetAttribute(attn_kernel, cudaFuncAttributeMaxDynamicSharedMemorySize,
                         ATTN_SMEM_BYTES);
    attn_kernel<<<dim3(S_LEN / QT, NH, B_DIM), 256, ATTN_SMEM_BYTES>>>(qr, kr, vraw, qraw);

    // Output projection (tf32 tensor cores)
    gemm_tf32<<<dim3(HID / 128, MROWS / 128), 256>>>(qraw, Wo, out, HID, NQ);
}

// round 5
// speedup vs baseline: 2.1270x; 1.3671x over previous
#include <cuda_runtime.h>
#include <cuda_bf16.h>
#include <stdint.h>
#include <math.h>

#define B_DIM   2
#define S_LEN   4096
#define HID     640
#define NH      4
#define HD      256
#define WIN     512
#define NQ      (NH * HD)          // 1024
#define MROWS   (B_DIM * S_LEN)    // 8192
#define SCALING 0.0625f            // 256^-0.5
#define SOFTCAP 50.0f
#define EPS_RMS 1e-6f
#define QT      64
#define KT      64

typedef unsigned int u32;

// ---------------------------------------------------------------------------
// Scratch (static device globals: allocation-free rule)
// ---------------------------------------------------------------------------
__device__ float g_Qraw[(size_t)MROWS * NQ];   // QKV gemm out; later reused as attn output
__device__ float g_Kraw[(size_t)MROWS * HD];
__device__ float g_Vraw[(size_t)MROWS * HD];
__device__ float g_Qr[(size_t)MROWS * NQ];     // [B][NH][S][HD], normed+roped, pre-scaled
__device__ float g_Kr[(size_t)MROWS * HD];     // [B][S][HD], normed+roped

// ===========================================================================
// TF32 tensor-core GEMM (unchanged from R4).
// ===========================================================================
#define GSTRIDE 136
#define GBUF    (16 * GSTRIDE)
#define ASW(k, m) ((k) * GSTRIDE + ((m) ^ ((((k) >> 2) & 3) << 3)))

__device__ __forceinline__ u32 f2tf32(float x) {
    u32 r;
    asm("cvt.rna.tf32.f32 %0, %1;" : "=r"(r) : "f"(x));
    return r;
}

__device__ __forceinline__ void mma_tf32(float* c,
    u32 a0, u32 a1, u32 a2, u32 a3, u32 b0, u32 b1)
{
    asm volatile(
        "mma.sync.aligned.m16n8k8.row.col.f32.tf32.tf32.f32 "
        "{%0,%1,%2,%3}, {%4,%5,%6,%7}, {%8,%9}, {%0,%1,%2,%3};"
        : "+f"(c[0]), "+f"(c[1]), "+f"(c[2]), "+f"(c[3])
        : "r"(a0), "r"(a1), "r"(a2), "r"(a3), "r"(b0), "r"(b1));
}

__device__ __forceinline__ void gemm_body(
    const float* __restrict__ A, const float* __restrict__ Bm,
    float* __restrict__ C, int N, int K, int bm, int bn,
    u32* As, u32* Bs)
{
    const int t    = threadIdx.x;
    const int warp = t >> 5, lane = t & 31;
    const int g    = lane >> 2, tc = lane & 3;
    const int wm   = (warp & 1) * 64;
    const int wn   = (warp >> 1) * 32;

    const int ar = t >> 2;
    const int ak = (t & 3) << 2;
    const int br = t >> 4;
    const int bc = (t & 15) << 2;

    float acc[4][4][4];
#pragma unroll
    for (int i = 0; i < 4; i++)
#pragma unroll
        for (int j = 0; j < 4; j++)
#pragma unroll
            for (int r = 0; r < 4; r++) acc[i][j][r] = 0.f;

    const int ktiles = K >> 4;

    float4 a0, a1, b0, b1;
    {
        const float* Ap = A + (size_t)(bm + ar) * K + ak;
        a0 = *(const float4*)Ap;
        a1 = *(const float4*)(Ap + (size_t)64 * K);
        const float* Bp = Bm + (size_t)br * N + bn + bc;
        b0 = *(const float4*)Bp;
        b1 = *(const float4*)(Bp + 64);
        u32* a_s = As;
        a_s[ASW(ak + 0, ar)] = f2tf32(a0.x);
        a_s[ASW(ak + 1, ar)] = f2tf32(a0.y);
        a_s[ASW(ak + 2, ar)] = f2tf32(a0.z);
        a_s[ASW(ak + 3, ar)] = f2tf32(a0.w);
        a_s[ASW(ak + 0, ar + 64)] = f2tf32(a1.x);
        a_s[ASW(ak + 1, ar + 64)] = f2tf32(a1.y);
        a_s[ASW(ak + 2, ar + 64)] = f2tf32(a1.z);
        a_s[ASW(ak + 3, ar + 64)] = f2tf32(a1.w);
        u32* b_s = Bs;
        b_s[br * GSTRIDE + bc + 0]  = f2tf32(b0.x);
        b_s[br * GSTRIDE + bc + 1]  = f2tf32(b0.y);
        b_s[br * GSTRIDE + bc + 2]  = f2tf32(b0.z);
        b_s[br * GSTRIDE + bc + 3]  = f2tf32(b0.w);
        b_s[br * GSTRIDE + bc + 64] = f2tf32(b1.x);
        b_s[br * GSTRIDE + bc + 65] = f2tf32(b1.y);
        b_s[br * GSTRIDE + bc + 66] = f2tf32(b1.z);
        b_s[br * GSTRIDE + bc + 67] = f2tf32(b1.w);
    }
    __syncthreads();

    int buf = 0;
    for (int kt = 0; kt < ktiles; kt++) {
        const bool have = (kt + 1) < ktiles;
        if (have) {
            const int k0 = (kt + 1) << 4;
            const float* Ap = A + (size_t)(bm + ar) * K + k0 + ak;
            a0 = *(const float4*)Ap;
            a1 = *(const float4*)(Ap + (size_t)64 * K);
            const float* Bp = Bm + (size_t)(k0 + br) * N + bn + bc;
            b0 = *(const float4*)Bp;
            b1 = *(const float4*)(Bp + 64);
        }

        {
            const u32* a_s = As + buf * GBUF;
            const u32* b_s = Bs + buf * GBUF;
#pragma unroll
            for (int ks = 0; ks < 2; ks++) {
                const int kc0 = ks * 8 + tc;
                const int kc1 = kc0 + 4;
                u32 af[4][4], bf[4][2];
#pragma unroll
                for (int mt = 0; mt < 4; mt++) {
                    const int m = wm + mt * 16 + g;
                    af[mt][0] = a_s[ASW(kc0, m)];
                    af[mt][1] = a_s[ASW(kc0, m + 8)];
                    af[mt][2] = a_s[ASW(kc1, m)];
                    af[mt][3] = a_s[ASW(kc1, m + 8)];
                }
#pragma unroll
                for (int nt = 0; nt < 4; nt++) {
                    const int n = wn + nt * 8 + g;
                    bf[nt][0] = b_s[kc0 * GSTRIDE + n];
                    bf[nt][1] = b_s[kc1 * GSTRIDE + n];
                }
#pragma unroll
                for (int mt = 0; mt < 4; mt++)
#pragma unroll
                    for (int nt = 0; nt < 4; nt++)
                        mma_tf32(acc[mt][nt], af[mt][0], af[mt][1], af[mt][2], af[mt][3],
                                 bf[nt][0], bf[nt][1]);
            }
        }

        if (have) {
            u32* a_s = As + (buf ^ 1) * GBUF;
            a_s[ASW(ak + 0, ar)] = f2tf32(a0.x);
            a_s[ASW(ak + 1, ar)] = f2tf32(a0.y);
            a_s[ASW(ak + 2, ar)] = f2tf32(a0.z);
            a_s[ASW(ak + 3, ar)] = f2tf32(a0.w);
            a_s[ASW(ak + 0, ar + 64)] = f2tf32(a1.x);
            a_s[ASW(ak + 1, ar + 64)] = f2tf32(a1.y);
            a_s[ASW(ak + 2, ar + 64)] = f2tf32(a1.z);
            a_s[ASW(ak + 3, ar + 64)] = f2tf32(a1.w);
            u32* b_s = Bs + (buf ^ 1) * GBUF;
            b_s[br * GSTRIDE + bc + 0]  = f2tf32(b0.x);
            b_s[br * GSTRIDE + bc + 1]  = f2tf32(b0.y);
            b_s[br * GSTRIDE + bc + 2]  = f2tf32(b0.z);
            b_s[br * GSTRIDE + bc + 3]  = f2tf32(b0.w);
            b_s[br * GSTRIDE + bc + 64] = f2tf32(b1.x);
            b_s[br * GSTRIDE + bc + 65] = f2tf32(b1.y);
            b_s[br * GSTRIDE + bc + 66] = f2tf32(b1.z);
            b_s[br * GSTRIDE + bc + 67] = f2tf32(b1.w);
        }
        __syncthreads();
        buf ^= 1;
    }

#pragma unroll
    for (int mt = 0; mt < 4; mt++) {
        const int row0 = bm + wm + mt * 16 + g;
#pragma unroll
        for (int nt = 0; nt < 4; nt++) {
            const int col = bn + wn + nt * 8 + 2 * tc;
            float2 lo = make_float2(acc[mt][nt][0], acc[mt][nt][1]);
            float2 hi = make_float2(acc[mt][nt][2], acc[mt][nt][3]);
            *(float2*)&C[(size_t)row0 * N + col]       = lo;
            *(float2*)&C[(size_t)(row0 + 8) * N + col] = hi;
        }
    }
}

__global__ void __launch_bounds__(256, 2) gemm_qkv_tf32(
    const float* __restrict__ A,
    const float* __restrict__ Wq, const float* __restrict__ Wk,
    const float* __restrict__ Wv,
    float* __restrict__ Qo, float* __restrict__ Ko, float* __restrict__ Vo)
{
    __shared__ u32 As[2 * GBUF];
    __shared__ u32 Bs[2 * GBUF];
    const int nb = blockIdx.x;
    const float* Bm; float* C; int N, bn;
    if (nb < 8)       { Bm = Wq; C = Qo; N = NQ;  bn = nb * 128; }
    else if (nb < 10) { Bm = Wk; C = Ko; N = HD;  bn = (nb - 8) * 128; }
    else              { Bm = Wv; C = Vo; N = HD;  bn = (nb - 10) * 128; }
    gemm_body(A, Bm, C, N, HID, blockIdx.y * 128, bn, As, Bs);
}

__global__ void __launch_bounds__(256, 2) gemm_tf32(
    const float* __restrict__ A, const float* __restrict__ Bm,
    float* __restrict__ C, int N, int K)
{
    __shared__ u32 As[2 * GBUF];
    __shared__ u32 Bs[2 * GBUF];
    gemm_body(A, Bm, C, N, K, blockIdx.y * 128, blockIdx.x * 128, As, Bs);
}

// ---------------------------------------------------------------------------
// RMSNorm + RoPE (unchanged).
// ---------------------------------------------------------------------------
__global__ void __launch_bounds__(256) normrope_kernel(
    const float* __restrict__ Qraw, const float* __restrict__ Kraw,
    const float* __restrict__ cosb, const float* __restrict__ sinb,
    const float* __restrict__ qw,   const float* __restrict__ kw,
    float* __restrict__ Qo, float* __restrict__ Ko)
{
    __shared__ float xbuf[HD];
    __shared__ float red[8];

    const int bs   = blockIdx.x;
    const int b    = bs / S_LEN;
    const int sIdx = bs % S_LEN;
    const int t    = threadIdx.x;
    const int lane = t & 31, warp = t >> 5;

    const float c   = cosb[(size_t)sIdx * HD + t];
    const float sn  = sinb[(size_t)sIdx * HD + t];
    const float qwv = 1.0f + qw[t];
    const float kwv = 1.0f + kw[t];

#pragma unroll
    for (int h = 0; h < NH + 1; h++) {
        float x = (h < NH) ? Qraw[(size_t)bs * NQ + h * HD + t]
                           : Kraw[(size_t)bs * HD + t];
        float ss = x * x;
#pragma unroll
        for (int o = 16; o > 0; o >>= 1) ss += __shfl_xor_sync(0xffffffffu, ss, o);
        if (lane == 0) red[warp] = ss;
        __syncthreads();
        float tot = 0.f;
#pragma unroll
        for (int w = 0; w < 8; w++) tot += red[w];
        float inv = rsqrtf(tot * (1.0f / HD) + EPS_RMS);
        float xn  = x * inv * ((h < NH) ? qwv : kwv);
        xbuf[t] = xn;
        __syncthreads();
        float other = (t < 128) ? xbuf[t + 128] : xbuf[t - 128];
        float rot   = (t < 128) ? (xn * c - other * sn) : (xn * c + other * sn);
        if (h < NH) Qo[(((size_t)b * NH + h) * S_LEN + sIdx) * HD + t] = rot * SCALING;
        else        Ko[((size_t)b * S_LEN + sIdx) * HD + t]            = rot;
        __syncthreads();
    }
}

// ===========================================================================
// Tensor-core attention: bf16x3 split-precision mma for QK^T and P.V.
// 8 warps; QK warp tile 16q x 32k (warp=(rg,kh)); PV warp tile 16q x 128d
// (warp=(rg,dh)). All smem planes packed bf16x2 with XOR-4g swizzle
// (conflict-free fragment loads). Online softmax; stats shared via smem.
// ===========================================================================
#define ATT_QHI 0
#define ATT_QLO 8192
#define ATT_KHI 16384
#define ATT_KLO 24576
#define ATT_VHI 32768
#define ATT_VLO 40960
#define ATT_PHI 49152
#define ATT_PLO 51200
#define ATT_MRED 53248          // 64*2 floats
#define ATT_SRED 53376          // 64*2 floats
#define ATT_SMEM_U32 53504
#define ATT_SMEM_BYTES (ATT_SMEM_U32 * 4)   // 214016

__device__ __forceinline__ void mma_bf16(float* c,
    u32 a0, u32 a1, u32 a2, u32 a3, u32 b0, u32 b1)
{
    asm volatile(
        "mma.sync.aligned.m16n8k16.row.col.f32.bf16.bf16.f32 "
        "{%0,%1,%2,%3}, {%4,%5,%6,%7}, {%8,%9}, {%0,%1,%2,%3};"
        : "+f"(c[0]), "+f"(c[1]), "+f"(c[2]), "+f"(c[3])
        : "r"(a0), "r"(a1), "r"(a2), "r"(a3), "r"(b0), "r"(b1));
}

// split two floats into packed bf16x2 hi and lo planes
__device__ __forceinline__ void split2(float x, float y, u32& hi, u32& lo) {
    __nv_bfloat16 hx = __float2bfloat16_rn(x);
    __nv_bfloat16 hy = __float2bfloat16_rn(y);
    float rx = x - __bfloat162float(hx);
    float ry = y - __bfloat162float(hy);
    __nv_bfloat162 hp = __halves2bfloat162(hx, hy);
    hi = *reinterpret_cast<u32*>(&hp);
    __nv_bfloat162 lp = __floats2bfloat162_rn(rx, ry);
    lo = *reinterpret_cast<u32*>(&lp);
}

// load a 64x256 fp32 tile (row stride HD) -> hi/lo planes [64][128] u32, swizzled
__device__ __forceinline__ void att_load_tile(const float* __restrict__ src,
                                              u32* hi, u32* lo, int t)
{
    const int r  = t >> 2;
    const int sw = 4 * (r & 7);
    const float* row = src + (size_t)r * HD;
    u32* hrow = hi + r * 128;
    u32* lrow = lo + r * 128;
#pragma unroll
    for (int i = 0; i < 16; i++) {
        int d = (t & 3) * 4 + i * 16;
        float4 v = *(const float4*)(row + d);
        int c = (d >> 1) ^ sw;
        u32 h0, l0, h1, l1;
        split2(v.x, v.y, h0, l0);
        split2(v.z, v.w, h1, l1);
        hrow[c] = h0; hrow[c + 1] = h1;
        lrow[c] = l0; lrow[c + 1] = l1;
    }
}

// load V tile transposed: Vt[d][key-pair] hi/lo [256][32] u32, swizzled
__device__ __forceinline__ void att_load_vt(const float* __restrict__ src,
                                            u32* hi, u32* lo, int t)
{
    const int w  = t >> 5;
    const int kp = t & 31;
    const float* r0 = src + (size_t)(2 * kp) * HD;
    const float* r1 = r0 + HD;
#pragma unroll
    for (int i = 0; i < 8; i++) {
        int d0 = w * 32 + i * 4;
        float4 a = *(const float4*)(r0 + d0);
        float4 b = *(const float4*)(r1 + d0);
        float av[4] = {a.x, a.y, a.z, a.w};
        float bv[4] = {b.x, b.y, b.z, b.w};
#pragma unroll
        for (int l = 0; l < 4; l++) {
            int d = d0 + l;
            u32 h, lw;
            split2(av[l], bv[l], h, lw);
            int idx = d * 32 + (kp ^ (4 * (d & 7)));
            hi[idx] = h; lo[idx] = lw;
        }
    }
}

__global__ void __launch_bounds__(256, 1) attn_mma_kernel(
    const float* __restrict__ Q,   // [B][NH][S][HD], pre-scaled
    const float* __restrict__ Kr,  // [B][S][HD]
    const float* __restrict__ V,   // [B*S][HD]
    float* __restrict__ O)         // [B*S][NQ]
{
    extern __shared__ u32 smu[];
    u32* QHI = smu + ATT_QHI;  u32* QLO = smu + ATT_QLO;
    u32* KHI = smu + ATT_KHI;  u32* KLO = smu + ATT_KLO;
    u32* VHI = smu + ATT_VHI;  u32* VLO = smu + ATT_VLO;
    u32* PHI = smu + ATT_PHI;  u32* PLO = smu + ATT_PLO;
    float* MRED = (float*)(smu + ATT_MRED);
    float* SRED = (float*)(smu + ATT_SRED);

    const int qb = blockIdx.x, h = blockIdx.y, b = blockIdx.z;
    const int q0 = qb * QT;
    const int t = threadIdx.x, lane = t & 31, warp = t >> 5;
    const int g = lane >> 2, tc = lane & 3;
    const int rg = warp >> 1, kh = warp & 1;   // kh doubles as d-half for PV
    const int row0 = 16 * rg + g;
    const int sa = 4 * g;

    att_load_tile(Q + (((size_t)b * NH + h) * S_LEN + q0) * HD, QHI, QLO, t);

    float m0 = -1e30f, m1 = -1e30f, l0 = 0.f, l1 = 0.f;
    float o[16][4];
#pragma unroll
    for (int i = 0; i < 16; i++)
#pragma unroll
        for (int e = 0; e < 4; e++) o[i][e] = 0.f;

    const int kt_lo = (qb >= 8) ? (qb - 8) : 0;
    for (int kt = kt_lo; kt <= qb; kt++) {
        const int j0 = kt * KT;
        __syncthreads();   // prev iteration done with K/V/P smem
        att_load_tile(Kr + ((size_t)b * S_LEN + j0) * HD, KHI, KLO, t);
        att_load_vt(V + ((size_t)b * S_LEN + j0) * HD, VHI, VLO, t);
        __syncthreads();

        // ---- QK^T: S[16 x 32] per warp ----
        float s[4][4];
#pragma unroll
        for (int nt = 0; nt < 4; nt++)
#pragma unroll
            for (int e = 0; e < 4; e++) s[nt][e] = 0.f;

        const u32* qh0 = QHI + row0 * 128;
        const u32* qh8 = qh0 + 8 * 128;
        const u32* ql0 = QLO + row0 * 128;
        const u32* ql8 = ql0 + 8 * 128;
        const u32* kb_h = KHI + (32 * kh + g) * 128;
        const u32* kb_l = KLO + (32 * kh + g) * 128;

#pragma unroll 4
        for (int ks = 0; ks < 16; ks++) {
            const int c0 = (ks * 8 + tc) ^ sa;
            const int c1 = (ks * 8 + 4 + tc) ^ sa;
            u32 ah0 = qh0[c0], ah1 = qh8[c0], ah2 = qh0[c1], ah3 = qh8[c1];
            u32 al0 = ql0[c0], al1 = ql8[c0], al2 = ql0[c1], al3 = ql8[c1];
#pragma unroll
            for (int nt = 0; nt < 4; nt++) {
                const u32* kp_h = kb_h + nt * 8 * 128;
                const u32* kp_l = kb_l + nt * 8 * 128;
                u32 bh0 = kp_h[c0], bh1 = kp_h[c1];
                u32 bl0 = kp_l[c0], bl1 = kp_l[c1];
                mma_bf16(s[nt], ah0, ah1, ah2, ah3, bh0, bh1);
                mma_bf16(s[nt], ah0, ah1, ah2, ah3, bl0, bl1);
                mma_bf16(s[nt], al0, al1, al2, al3, bh0, bh1);
            }
        }

        // ---- softcap + window mask + per-warp row stats ----
        float tmax0 = -1e30f, tmax1 = -1e30f;
#pragma unroll
        for (int nt = 0; nt < 4; nt++) {
#pragma unroll
            for (int e = 0; e < 4; e++) {
                const int col = j0 + 32 * kh + nt * 8 + 2 * tc + (e & 1);
                const int row = q0 + row0 + (e >> 1) * 8;
                const bool ok = (col <= row) && (col > row - WIN);
                float x = s[nt][e];
                float ex = __expf(x * (2.0f / SOFTCAP));
                float sc = SOFTCAP - SOFTCAP * 2.0f * __frcp_rn(ex + 1.0f);
                float val = ok ? sc : -1e30f;
                s[nt][e] = val;
                if (e >> 1) tmax1 = fmaxf(tmax1, val);
                else        tmax0 = fmaxf(tmax0, val);
            }
        }
        tmax0 = fmaxf(tmax0, __shfl_xor_sync(0xffffffffu, tmax0, 1));
        tmax0 = fmaxf(tmax0, __shfl_xor_sync(0xffffffffu, tmax0, 2));
        tmax1 = fmaxf(tmax1, __shfl_xor_sync(0xffffffffu, tmax1, 1));
        tmax1 = fmaxf(tmax1, __shfl_xor_sync(0xffffffffu, tmax1, 2));
        MRED[(row0)     * 2 + kh] = tmax0;
        MRED[(row0 + 8) * 2 + kh] = tmax1;
        __syncthreads();

        const float nm0 = fmaxf(m0, fmaxf(MRED[row0 * 2], MRED[row0 * 2 + 1]));
        const float nm1 = fmaxf(m1, fmaxf(MRED[(row0 + 8) * 2], MRED[(row0 + 8) * 2 + 1]));
        const float f0 = __expf(m0 - nm0);
        const float f1 = __expf(m1 - nm1);
        m0 = nm0; m1 = nm1;

        // ---- p = exp(s - m), write P hi/lo to smem, partial row sums ----
        float tsum0 = 0.f, tsum1 = 0.f;
        u32* ph0 = PHI + row0 * 32;
        u32* ph8 = ph0 + 8 * 32;
        u32* pl0 = PLO + row0 * 32;
        u32* pl8 = pl0 + 8 * 32;
#pragma unroll
        for (int nt = 0; nt < 4; nt++) {
            float p00 = (s[nt][0] > -1e29f) ? __expf(s[nt][0] - nm0) : 0.f;
            float p01 = (s[nt][1] > -1e29f) ? __expf(s[nt][1] - nm0) : 0.f;
            float p10 = (s[nt][2] > -1e29f) ? __expf(s[nt][2] - nm1) : 0.f;
            float p11 = (s[nt][3] > -1e29f) ? __expf(s[nt][3] - nm1) : 0.f;
            tsum0 += p00 + p01;
            tsum1 += p10 + p11;
            const int c = (16 * kh + nt * 4 + tc) ^ sa;
            u32 hv, lv;
            split2(p00, p01, hv, lv);
            ph0[c] = hv; pl0[c] = lv;
            split2(p10, p11, hv, lv);
            ph8[c] = hv; pl8[c] = lv;
        }
        tsum0 += __shfl_xor_sync(0xffffffffu, tsum0, 1);
        tsum0 += __shfl_xor_sync(0xffffffffu, tsum0, 2);
        tsum1 += __shfl_xor_sync(0xffffffffu, tsum1, 1);
        tsum1 += __shfl_xor_sync(0xffffffffu, tsum1, 2);
        SRED[(row0)     * 2 + kh] = tsum0;
        SRED[(row0 + 8) * 2 + kh] = tsum1;
        __syncthreads();

        l0 = l0 * f0 + SRED[row0 * 2] + SRED[row0 * 2 + 1];
        l1 = l1 * f1 + SRED[(row0 + 8) * 2] + SRED[(row0 + 8) * 2 + 1];

        // rescale O
#pragma unroll
        for (int nt = 0; nt < 16; nt++) {
            o[nt][0] *= f0; o[nt][1] *= f0;
            o[nt][2] *= f1; o[nt][3] *= f1;
        }

        // ---- P.V: O[16 x 128] per warp (d-half = kh) ----
        const u32* pa_h0 = PHI + row0 * 32;
        const u32* pa_h8 = pa_h0 + 8 * 32;
        const u32* pa_l0 = PLO + row0 * 32;
        const u32* pa_l8 = pa_l0 + 8 * 32;
        const u32* vb_h = VHI + (128 * kh + g) * 32;
        const u32* vb_l = VLO + (128 * kh + g) * 32;

#pragma unroll
        for (int ks = 0; ks < 4; ks++) {
            const int c0 = (ks * 8 + tc) ^ sa;
            const int c1 = (ks * 8 + 4 + tc) ^ sa;
            u32 ah0 = pa_h0[c0], ah1 = pa_h8[c0], ah2 = pa_h0[c1], ah3 = pa_h8[c1];
            u32 al0 = pa_l0[c0], al1 = pa_l8[c0], al2 = pa_l0[c1], al3 = pa_l8[c1];
#pragma unroll
            for (int nt = 0; nt < 16; nt++) {
                const u32* vp_h = vb_h + nt * 8 * 32;
                const u32* vp_l = vb_l + nt * 8 * 32;
                u32 bh0 = vp_h[c0], bh1 = vp_h[c1];
                u32 bl0 = vp_l[c0], bl1 = vp_l[c1];
                mma_bf16(o[nt], ah0, ah1, ah2, ah3, bh0, bh1);
                mma_bf16(o[nt], al0, al1, al2, al3, bh0, bh1);
                mma_bf16(o[nt], ah0, ah1, ah2, ah3, bl0, bl1);
            }
        }
    }

    // ---- epilogue ----
    const float inv0 = __frcp_rn(l0);
    const float inv1 = __frcp_rn(l1);
    float* O0 = O + ((size_t)b * S_LEN + q0 + row0) * NQ + h * HD + 128 * kh;
    float* O8 = O0 + (size_t)8 * NQ;
#pragma unroll
    for (int nt = 0; nt < 16; nt++) {
        const int d = nt * 8 + 2 * tc;
        *(float2*)(O0 + d) = make_float2(o[nt][0] * inv0, o[nt][1] * inv0);
        *(float2*)(O8 + d) = make_float2(o[nt][2] * inv1, o[nt][3] * inv1);
    }
}

// ---------------------------------------------------------------------------
// Launch
// ---------------------------------------------------------------------------
extern "C" void kernel_launch(void* const* d_in, const int* in_sizes, int n_in,
                              void* d_out, int out_size)
{
    (void)in_sizes; (void)n_in; (void)out_size;
    const float* hidden = (const float*)d_in[0];
    const float* cosb   = (const float*)d_in[1];
    const float* sinb   = (const float*)d_in[2];
    // d_in[3] = attention_mask: analytic sliding-window mask used instead
    const float* Wq = (const float*)d_in[4];
    const float* Wk = (const float*)d_in[5];
    const float* Wv = (const float*)d_in[6];
    const float* Wo = (const float*)d_in[7];
    const float* qw = (const float*)d_in[8];
    const float* kw = (const float*)d_in[9];
    float* out = (float*)d_out;

    float *qraw, *kraw, *vraw, *qr, *kr;
    cudaGetSymbolAddress((void**)&qraw, g_Qraw);
    cudaGetSymbolAddress((void**)&kraw, g_Kraw);
    cudaGetSymbolAddress((void**)&vraw, g_Vraw);
    cudaGetSymbolAddress((void**)&qr, g_Qr);
    cudaGetSymbolAddress((void**)&kr, g_Kr);

    // Fused QKV projection (tf32 tensor cores)
    gemm_qkv_tf32<<<dim3(12, MROWS / 128), 256>>>(hidden, Wq, Wk, Wv, qraw, kraw, vraw);

    // RMSNorm + RoPE (Q pre-scaled by SCALING)
    normrope_kernel<<<MROWS, 256>>>(qraw, kraw, cosb, sinb, qw, kw, qr, kr);

    // Tensor-core windowed softcap attention (writes into qraw)
    cudaFuncSetAttribute(attn_mma_kernel, cudaFuncAttributeMaxDynamicSharedMemorySize,
                         ATT_SMEM_BYTES);
    attn_mma_kernel<<<dim3(S_LEN / QT, NH, B_DIM), 256, ATT_SMEM_BYTES>>>(qr, kr, vraw, qraw);

    // Output projection (tf32 tensor cores)
    gemm_tf32<<<dim3(HID / 128, MROWS / 128), 256>>>(qraw, Wo, out, HID, NQ);
}

// round 6
// speedup vs baseline: 2.1745x; 1.0223x over previous
#include <cuda_runtime.h>
#include <cuda_bf16.h>
#include <stdint.h>
#include <math.h>

#define B_DIM   2
#define S_LEN   4096
#define HID     640
#define NH      4
#define HD      256
#define WIN     512
#define NQ      (NH * HD)          // 1024
#define MROWS   (B_DIM * S_LEN)    // 8192
#define SCALING 0.0625f            // 256^-0.5
#define SOFTCAP 50.0f
#define EPS_RMS 1e-6f
#define QT      64
#define KT      64

typedef unsigned int u32;

// ---------------------------------------------------------------------------
// Scratch (static device globals: allocation-free rule)
// ---------------------------------------------------------------------------
__device__ float g_Qraw[(size_t)MROWS * NQ];   // QKV gemm out; later reused as attn output
__device__ float g_Kraw[(size_t)MROWS * HD];
__device__ float g_Vraw[(size_t)MROWS * HD];
__device__ float g_Qr[(size_t)MROWS * NQ];     // [B][NH][S][HD], normed+roped, pre-scaled
__device__ float g_Kr[(size_t)MROWS * HD];     // [B][S][HD], normed+roped

// ===========================================================================
// TF32 tensor-core GEMM. Templated on BN (block n-tile width: 128 or 64).
// 128xBNx16 block tile, 256 threads (8 warps), warp tile 64x(BN/4),
// mma.sync.aligned.m16n8k8. XOR-swizzled A, double-buffered smem.
// ===========================================================================
#define GSTRIDE 136
#define GBUF    (16 * GSTRIDE)
#define ASW(k, m) ((k) * GSTRIDE + ((m) ^ ((((k) >> 2) & 3) << 3)))

__device__ __forceinline__ u32 f2tf32(float x) {
    u32 r;
    asm("cvt.rna.tf32.f32 %0, %1;" : "=r"(r) : "f"(x));
    return r;
}

__device__ __forceinline__ void mma_tf32(float* c,
    u32 a0, u32 a1, u32 a2, u32 a3, u32 b0, u32 b1)
{
    asm volatile(
        "mma.sync.aligned.m16n8k8.row.col.f32.tf32.tf32.f32 "
        "{%0,%1,%2,%3}, {%4,%5,%6,%7}, {%8,%9}, {%0,%1,%2,%3};"
        : "+f"(c[0]), "+f"(c[1]), "+f"(c[2]), "+f"(c[3])
        : "r"(a0), "r"(a1), "r"(a2), "r"(a3), "r"(b0), "r"(b1));
}

template<int BN>
__device__ __forceinline__ void gemm_body(
    const float* __restrict__ A, const float* __restrict__ Bm,
    float* __restrict__ C, int N, int K, int bm, int bn,
    u32* As, u32* Bs)
{
    constexpr int NT = BN / 32;       // n8-tiles per warp
    const int t    = threadIdx.x;
    const int warp = t >> 5, lane = t & 31;
    const int g    = lane >> 2, tc = lane & 3;
    const int wm   = (warp & 1) * 64;
    const int wn   = (warp >> 1) * (BN / 4);

    const int ar = t >> 2;
    const int ak = (t & 3) << 2;
    const int br = t >> 4;
    const int bc = (t & 15) << 2;

    float acc[4][NT][4];
#pragma unroll
    for (int i = 0; i < 4; i++)
#pragma unroll
        for (int j = 0; j < NT; j++)
#pragma unroll
            for (int r = 0; r < 4; r++) acc[i][j][r] = 0.f;

    const int ktiles = K >> 4;

    float4 a0, a1, b0, b1;
    {
        const float* Ap = A + (size_t)(bm + ar) * K + ak;
        a0 = *(const float4*)Ap;
        a1 = *(const float4*)(Ap + (size_t)64 * K);
        const float* Bp = Bm + (size_t)br * N + bn + bc;
        b0 = *(const float4*)Bp;
        if (BN == 128) b1 = *(const float4*)(Bp + 64);
        u32* a_s = As;
        a_s[ASW(ak + 0, ar)] = f2tf32(a0.x);
        a_s[ASW(ak + 1, ar)] = f2tf32(a0.y);
        a_s[ASW(ak + 2, ar)] = f2tf32(a0.z);
        a_s[ASW(ak + 3, ar)] = f2tf32(a0.w);
        a_s[ASW(ak + 0, ar + 64)] = f2tf32(a1.x);
        a_s[ASW(ak + 1, ar + 64)] = f2tf32(a1.y);
        a_s[ASW(ak + 2, ar + 64)] = f2tf32(a1.z);
        a_s[ASW(ak + 3, ar + 64)] = f2tf32(a1.w);
        u32* b_s = Bs;
        b_s[br * GSTRIDE + bc + 0]  = f2tf32(b0.x);
        b_s[br * GSTRIDE + bc + 1]  = f2tf32(b0.y);
        b_s[br * GSTRIDE + bc + 2]  = f2tf32(b0.z);
        b_s[br * GSTRIDE + bc + 3]  = f2tf32(b0.w);
        if (BN == 128) {
            b_s[br * GSTRIDE + bc + 64] = f2tf32(b1.x);
            b_s[br * GSTRIDE + bc + 65] = f2tf32(b1.y);
            b_s[br * GSTRIDE + bc + 66] = f2tf32(b1.z);
            b_s[br * GSTRIDE + bc + 67] = f2tf32(b1.w);
        }
    }
    __syncthreads();

    int buf = 0;
    for (int kt = 0; kt < ktiles; kt++) {
        const bool have = (kt + 1) < ktiles;
        if (have) {
            const int k0 = (kt + 1) << 4;
            const float* Ap = A + (size_t)(bm + ar) * K + k0 + ak;
            a0 = *(const float4*)Ap;
            a1 = *(const float4*)(Ap + (size_t)64 * K);
            const float* Bp = Bm + (size_t)(k0 + br) * N + bn + bc;
            b0 = *(const float4*)Bp;
            if (BN == 128) b1 = *(const float4*)(Bp + 64);
        }

        {
            const u32* a_s = As + buf * GBUF;
            const u32* b_s = Bs + buf * GBUF;
#pragma unroll
            for (int ks = 0; ks < 2; ks++) {
                const int kc0 = ks * 8 + tc;
                const int kc1 = kc0 + 4;
                u32 af[4][4], bf[NT][2];
#pragma unroll
                for (int mt = 0; mt < 4; mt++) {
                    const int m = wm + mt * 16 + g;
                    af[mt][0] = a_s[ASW(kc0, m)];
                    af[mt][1] = a_s[ASW(kc0, m + 8)];
                    af[mt][2] = a_s[ASW(kc1, m)];
                    af[mt][3] = a_s[ASW(kc1, m + 8)];
                }
#pragma unroll
                for (int nt = 0; nt < NT; nt++) {
                    const int n = wn + nt * 8 + g;
                    bf[nt][0] = b_s[kc0 * GSTRIDE + n];
                    bf[nt][1] = b_s[kc1 * GSTRIDE + n];
                }
#pragma unroll
                for (int mt = 0; mt < 4; mt++)
#pragma unroll
                    for (int nt = 0; nt < NT; nt++)
                        mma_tf32(acc[mt][nt], af[mt][0], af[mt][1], af[mt][2], af[mt][3],
                                 bf[nt][0], bf[nt][1]);
            }
        }

        if (have) {
            u32* a_s = As + (buf ^ 1) * GBUF;
            a_s[ASW(ak + 0, ar)] = f2tf32(a0.x);
            a_s[ASW(ak + 1, ar)] = f2tf32(a0.y);
            a_s[ASW(ak + 2, ar)] = f2tf32(a0.z);
            a_s[ASW(ak + 3, ar)] = f2tf32(a0.w);
            a_s[ASW(ak + 0, ar + 64)] = f2tf32(a1.x);
            a_s[ASW(ak + 1, ar + 64)] = f2tf32(a1.y);
            a_s[ASW(ak + 2, ar + 64)] = f2tf32(a1.z);
            a_s[ASW(ak + 3, ar + 64)] = f2tf32(a1.w);
            u32* b_s = Bs + (buf ^ 1) * GBUF;
            b_s[br * GSTRIDE + bc + 0]  = f2tf32(b0.x);
            b_s[br * GSTRIDE + bc + 1]  = f2tf32(b0.y);
            b_s[br * GSTRIDE + bc + 2]  = f2tf32(b0.z);
            b_s[br * GSTRIDE + bc + 3]  = f2tf32(b0.w);
            if (BN == 128) {
                b_s[br * GSTRIDE + bc + 64] = f2tf32(b1.x);
                b_s[br * GSTRIDE + bc + 65] = f2tf32(b1.y);
                b_s[br * GSTRIDE + bc + 66] = f2tf32(b1.z);
                b_s[br * GSTRIDE + bc + 67] = f2tf32(b1.w);
            }
        }
        __syncthreads();
        buf ^= 1;
    }

#pragma unroll
    for (int mt = 0; mt < 4; mt++) {
        const int row0 = bm + wm + mt * 16 + g;
#pragma unroll
        for (int nt = 0; nt < NT; nt++) {
            const int col = bn + wn + nt * 8 + 2 * tc;
            float2 lo = make_float2(acc[mt][nt][0], acc[mt][nt][1]);
            float2 hi = make_float2(acc[mt][nt][2], acc[mt][nt][3]);
            *(float2*)&C[(size_t)row0 * N + col]       = lo;
            *(float2*)&C[(size_t)(row0 + 8) * N + col] = hi;
        }
    }
}

__global__ void __launch_bounds__(256, 2) gemm_qkv_tf32(
    const float* __restrict__ A,
    const float* __restrict__ Wq, const float* __restrict__ Wk,
    const float* __restrict__ Wv,
    float* __restrict__ Qo, float* __restrict__ Ko, float* __restrict__ Vo)
{
    __shared__ u32 As[2 * GBUF];
    __shared__ u32 Bs[2 * GBUF];
    const int nb = blockIdx.x;
    const float* Bm; float* C; int N, bn;
    if (nb < 8)       { Bm = Wq; C = Qo; N = NQ;  bn = nb * 128; }
    else if (nb < 10) { Bm = Wk; C = Ko; N = HD;  bn = (nb - 8) * 128; }
    else              { Bm = Wv; C = Vo; N = HD;  bn = (nb - 10) * 128; }
    gemm_body<128>(A, Bm, C, N, HID, blockIdx.y * 128, bn, As, Bs);
}

// Output projection: 128x64 tiles (finer tail granularity).
__global__ void __launch_bounds__(256, 2) gemm_o_tf32(
    const float* __restrict__ A, const float* __restrict__ Bm,
    float* __restrict__ C, int N, int K)
{
    __shared__ u32 As[2 * GBUF];
    __shared__ u32 Bs[2 * GBUF];
    gemm_body<64>(A, Bm, C, N, K, blockIdx.y * 128, blockIdx.x * 64, As, Bs);
}

// ---------------------------------------------------------------------------
// RMSNorm + RoPE (unchanged).
// ---------------------------------------------------------------------------
__global__ void __launch_bounds__(256) normrope_kernel(
    const float* __restrict__ Qraw, const float* __restrict__ Kraw,
    const float* __restrict__ cosb, const float* __restrict__ sinb,
    const float* __restrict__ qw,   const float* __restrict__ kw,
    float* __restrict__ Qo, float* __restrict__ Ko)
{
    __shared__ float xbuf[HD];
    __shared__ float red[8];

    const int bs   = blockIdx.x;
    const int b    = bs / S_LEN;
    const int sIdx = bs % S_LEN;
    const int t    = threadIdx.x;
    const int lane = t & 31, warp = t >> 5;

    const float c   = cosb[(size_t)sIdx * HD + t];
    const float sn  = sinb[(size_t)sIdx * HD + t];
    const float qwv = 1.0f + qw[t];
    const float kwv = 1.0f + kw[t];

#pragma unroll
    for (int h = 0; h < NH + 1; h++) {
        float x = (h < NH) ? Qraw[(size_t)bs * NQ + h * HD + t]
                           : Kraw[(size_t)bs * HD + t];
        float ss = x * x;
#pragma unroll
        for (int o = 16; o > 0; o >>= 1) ss += __shfl_xor_sync(0xffffffffu, ss, o);
        if (lane == 0) red[warp] = ss;
        __syncthreads();
        float tot = 0.f;
#pragma unroll
        for (int w = 0; w < 8; w++) tot += red[w];
        float inv = rsqrtf(tot * (1.0f / HD) + EPS_RMS);
        float xn  = x * inv * ((h < NH) ? qwv : kwv);
        xbuf[t] = xn;
        __syncthreads();
        float other = (t < 128) ? xbuf[t + 128] : xbuf[t - 128];
        float rot   = (t < 128) ? (xn * c - other * sn) : (xn * c + other * sn);
        if (h < NH) Qo[(((size_t)b * NH + h) * S_LEN + sIdx) * HD + t] = rot * SCALING;
        else        Ko[((size_t)b * S_LEN + sIdx) * HD + t]            = rot;
        __syncthreads();
    }
}

// ===========================================================================
// Tensor-core attention (bf16x3 split), 512 threads / 16 warps.
// warp = (rg 0..3, kq 0..3). QK warp tile 16q x 16k; PV warp tile 16q x 64d.
// ===========================================================================
#define ATT_QHI 0
#define ATT_QLO 8192
#define ATT_KHI 16384
#define ATT_KLO 24576
#define ATT_VHI 32768
#define ATT_VLO 40960
#define ATT_PHI 49152
#define ATT_PLO 51200
#define ATT_MRED 53248          // 64*4 floats
#define ATT_SRED 53504          // 64*4 floats
#define ATT_SMEM_U32 53760
#define ATT_SMEM_BYTES (ATT_SMEM_U32 * 4)   // 215040

__device__ __forceinline__ void mma_bf16(float* c,
    u32 a0, u32 a1, u32 a2, u32 a3, u32 b0, u32 b1)
{
    asm volatile(
        "mma.sync.aligned.m16n8k16.row.col.f32.bf16.bf16.f32 "
        "{%0,%1,%2,%3}, {%4,%5,%6,%7}, {%8,%9}, {%0,%1,%2,%3};"
        : "+f"(c[0]), "+f"(c[1]), "+f"(c[2]), "+f"(c[3])
        : "r"(a0), "r"(a1), "r"(a2), "r"(a3), "r"(b0), "r"(b1));
}

__device__ __forceinline__ void split2(float x, float y, u32& hi, u32& lo) {
    __nv_bfloat16 hx = __float2bfloat16_rn(x);
    __nv_bfloat16 hy = __float2bfloat16_rn(y);
    float rx = x - __bfloat162float(hx);
    float ry = y - __bfloat162float(hy);
    __nv_bfloat162 hp = __halves2bfloat162(hx, hy);
    hi = *reinterpret_cast<u32*>(&hp);
    __nv_bfloat162 lp = __floats2bfloat162_rn(rx, ry);
    lo = *reinterpret_cast<u32*>(&lp);
}

// 64x256 fp32 tile -> hi/lo planes [64][128] u32, swizzled. 512 threads.
__device__ __forceinline__ void att_load_tile(const float* __restrict__ src,
                                              u32* hi, u32* lo, int t)
{
    const int r  = t >> 3;            // 0..63
    const int sw = 4 * (r & 7);
    const float* row = src + (size_t)r * HD;
    u32* hrow = hi + r * 128;
    u32* lrow = lo + r * 128;
#pragma unroll
    for (int i = 0; i < 8; i++) {
        int d = (t & 7) * 4 + i * 32;
        float4 v = *(const float4*)(row + d);
        int c = (d >> 1) ^ sw;
        u32 h0, l0, h1, l1;
        split2(v.x, v.y, h0, l0);
        split2(v.z, v.w, h1, l1);
        hrow[c] = h0; hrow[c + 1] = h1;
        lrow[c] = l0; lrow[c + 1] = l1;
    }
}

// V tile transposed: Vt[d][key-pair] hi/lo [256][32] u32, swizzled. 512 threads.
__device__ __forceinline__ void att_load_vt(const float* __restrict__ src,
                                            u32* hi, u32* lo, int t)
{
    const int w  = t >> 5;            // 0..15
    const int kp = t & 31;
    const float* r0 = src + (size_t)(2 * kp) * HD;
    const float* r1 = r0 + HD;
#pragma unroll
    for (int i = 0; i < 4; i++) {
        int d0 = w * 16 + i * 4;
        float4 a = *(const float4*)(r0 + d0);
        float4 b = *(const float4*)(r1 + d0);
        float av[4] = {a.x, a.y, a.z, a.w};
        float bv[4] = {b.x, b.y, b.z, b.w};
#pragma unroll
        for (int l = 0; l < 4; l++) {
            int d = d0 + l;
            u32 h, lw;
            split2(av[l], bv[l], h, lw);
            int idx = d * 32 + (kp ^ (4 * (d & 7)));
            hi[idx] = h; lo[idx] = lw;
        }
    }
}

__global__ void __launch_bounds__(512, 1) attn_mma_kernel(
    const float* __restrict__ Q,   // [B][NH][S][HD], pre-scaled
    const float* __restrict__ Kr,  // [B][S][HD]
    const float* __restrict__ V,   // [B*S][HD]
    float* __restrict__ O)         // [B*S][NQ]
{
    extern __shared__ u32 smu[];
    u32* QHI = smu + ATT_QHI;  u32* QLO = smu + ATT_QLO;
    u32* KHI = smu + ATT_KHI;  u32* KLO = smu + ATT_KLO;
    u32* VHI = smu + ATT_VHI;  u32* VLO = smu + ATT_VLO;
    u32* PHI = smu + ATT_PHI;  u32* PLO = smu + ATT_PLO;
    float* MRED = (float*)(smu + ATT_MRED);
    float* SRED = (float*)(smu + ATT_SRED);

    const int qb = blockIdx.x, h = blockIdx.y, b = blockIdx.z;
    const int q0 = qb * QT;
    const int t = threadIdx.x, lane = t & 31, warp = t >> 5;
    const int g = lane >> 2, tc = lane & 3;
    const int rg = warp >> 2, kq = warp & 3;   // kq: QK key quarter / PV d quarter
    const int row0 = 16 * rg + g;
    const int sa = 4 * g;

    att_load_tile(Q + (((size_t)b * NH + h) * S_LEN + q0) * HD, QHI, QLO, t);

    float m0 = -1e30f, m1 = -1e30f, l0 = 0.f, l1 = 0.f;
    float o[8][4];
#pragma unroll
    for (int i = 0; i < 8; i++)
#pragma unroll
        for (int e = 0; e < 4; e++) o[i][e] = 0.f;

    const int kt_lo = (qb >= 8) ? (qb - 8) : 0;
    for (int kt = kt_lo; kt <= qb; kt++) {
        const int j0 = kt * KT;
        __syncthreads();   // prev iteration done with K/V/P smem
        att_load_tile(Kr + ((size_t)b * S_LEN + j0) * HD, KHI, KLO, t);
        att_load_vt(V + ((size_t)b * S_LEN + j0) * HD, VHI, VLO, t);
        __syncthreads();

        // ---- QK^T: S[16 x 16] per warp ----
        float s[2][4];
#pragma unroll
        for (int nt = 0; nt < 2; nt++)
#pragma unroll
            for (int e = 0; e < 4; e++) s[nt][e] = 0.f;

        const u32* qh0 = QHI + row0 * 128;
        const u32* qh8 = qh0 + 8 * 128;
        const u32* ql0 = QLO + row0 * 128;
        const u32* ql8 = ql0 + 8 * 128;
        const u32* kb_h = KHI + (16 * kq + g) * 128;
        const u32* kb_l = KLO + (16 * kq + g) * 128;

#pragma unroll 4
        for (int ks = 0; ks < 16; ks++) {
            const int c0 = (ks * 8 + tc) ^ sa;
            const int c1 = (ks * 8 + 4 + tc) ^ sa;
            u32 ah0 = qh0[c0], ah1 = qh8[c0], ah2 = qh0[c1], ah3 = qh8[c1];
            u32 al0 = ql0[c0], al1 = ql8[c0], al2 = ql0[c1], al3 = ql8[c1];
#pragma unroll
            for (int nt = 0; nt < 2; nt++) {
                const u32* kp_h = kb_h + nt * 8 * 128;
                const u32* kp_l = kb_l + nt * 8 * 128;
                u32 bh0 = kp_h[c0], bh1 = kp_h[c1];
                u32 bl0 = kp_l[c0], bl1 = kp_l[c1];
                mma_bf16(s[nt], ah0, ah1, ah2, ah3, bh0, bh1);
                mma_bf16(s[nt], ah0, ah1, ah2, ah3, bl0, bl1);
                mma_bf16(s[nt], al0, al1, al2, al3, bh0, bh1);
            }
        }

        // ---- softcap + window mask + per-warp row stats ----
        float tmax0 = -1e30f, tmax1 = -1e30f;
#pragma unroll
        for (int nt = 0; nt < 2; nt++) {
#pragma unroll
            for (int e = 0; e < 4; e++) {
                const int col = j0 + 16 * kq + nt * 8 + 2 * tc + (e & 1);
                const int row = q0 + row0 + (e >> 1) * 8;
                const bool ok = (col <= row) && (col > row - WIN);
                float x = s[nt][e];
                float ex = __expf(x * (2.0f / SOFTCAP));
                float sc = SOFTCAP - SOFTCAP * 2.0f * __frcp_rn(ex + 1.0f);
                float val = ok ? sc : -1e30f;
                s[nt][e] = val;
                if (e >> 1) tmax1 = fmaxf(tmax1, val);
                else        tmax0 = fmaxf(tmax0, val);
            }
        }
        tmax0 = fmaxf(tmax0, __shfl_xor_sync(0xffffffffu, tmax0, 1));
        tmax0 = fmaxf(tmax0, __shfl_xor_sync(0xffffffffu, tmax0, 2));
        tmax1 = fmaxf(tmax1, __shfl_xor_sync(0xffffffffu, tmax1, 1));
        tmax1 = fmaxf(tmax1, __shfl_xor_sync(0xffffffffu, tmax1, 2));
        if (tc == 0) {
            MRED[(row0)     * 4 + kq] = tmax0;
            MRED[(row0 + 8) * 4 + kq] = tmax1;
        }
        __syncthreads();

        const float* mr0 = MRED + row0 * 4;
        const float* mr1 = MRED + (row0 + 8) * 4;
        const float nm0 = fmaxf(m0, fmaxf(fmaxf(mr0[0], mr0[1]), fmaxf(mr0[2], mr0[3])));
        const float nm1 = fmaxf(m1, fmaxf(fmaxf(mr1[0], mr1[1]), fmaxf(mr1[2], mr1[3])));
        const float f0 = __expf(m0 - nm0);
        const float f1 = __expf(m1 - nm1);
        m0 = nm0; m1 = nm1;

        // ---- p = exp(s - m), write P hi/lo to smem, partial row sums ----
        float tsum0 = 0.f, tsum1 = 0.f;
        u32* ph0 = PHI + row0 * 32;
        u32* ph8 = ph0 + 8 * 32;
        u32* pl0 = PLO + row0 * 32;
        u32* pl8 = pl0 + 8 * 32;
#pragma unroll
        for (int nt = 0; nt < 2; nt++) {
            float p00 = (s[nt][0] > -1e29f) ? __expf(s[nt][0] - nm0) : 0.f;
            float p01 = (s[nt][1] > -1e29f) ? __expf(s[nt][1] - nm0) : 0.f;
            float p10 = (s[nt][2] > -1e29f) ? __expf(s[nt][2] - nm1) : 0.f;
            float p11 = (s[nt][3] > -1e29f) ? __expf(s[nt][3] - nm1) : 0.f;
            tsum0 += p00 + p01;
            tsum1 += p10 + p11;
            const int c = (8 * kq + nt * 4 + tc) ^ sa;
            u32 hv, lv;
            split2(p00, p01, hv, lv);
            ph0[c] = hv; pl0[c] = lv;
            split2(p10, p11, hv, lv);
            ph8[c] = hv; pl8[c] = lv;
        }
        tsum0 += __shfl_xor_sync(0xffffffffu, tsum0, 1);
        tsum0 += __shfl_xor_sync(0xffffffffu, tsum0, 2);
        tsum1 += __shfl_xor_sync(0xffffffffu, tsum1, 1);
        tsum1 += __shfl_xor_sync(0xffffffffu, tsum1, 2);
        if (tc == 0) {
            SRED[(row0)     * 4 + kq] = tsum0;
            SRED[(row0 + 8) * 4 + kq] = tsum1;
        }
        __syncthreads();

        const float* sr0 = SRED + row0 * 4;
        const float* sr1 = SRED + (row0 + 8) * 4;
        l0 = l0 * f0 + sr0[0] + sr0[1] + sr0[2] + sr0[3];
        l1 = l1 * f1 + sr1[0] + sr1[1] + sr1[2] + sr1[3];

        // rescale O
#pragma unroll
        for (int nt = 0; nt < 8; nt++) {
            o[nt][0] *= f0; o[nt][1] *= f0;
            o[nt][2] *= f1; o[nt][3] *= f1;
        }

        // ---- P.V: O[16 x 64] per warp (d quarter = kq) ----
        const u32* pa_h0 = PHI + row0 * 32;
        const u32* pa_h8 = pa_h0 + 8 * 32;
        const u32* pa_l0 = PLO + row0 * 32;
        const u32* pa_l8 = pa_l0 + 8 * 32;
        const u32* vb_h = VHI + (64 * kq + g) * 32;
        const u32* vb_l = VLO + (64 * kq + g) * 32;

#pragma unroll
        for (int ks = 0; ks < 4; ks++) {
            const int c0 = (ks * 8 + tc) ^ sa;
            const int c1 = (ks * 8 + 4 + tc) ^ sa;
            u32 ah0 = pa_h0[c0], ah1 = pa_h8[c0], ah2 = pa_h0[c1], ah3 = pa_h8[c1];
            u32 al0 = pa_l0[c0], al1 = pa_l8[c0], al2 = pa_l0[c1], al3 = pa_l8[c1];
#pragma unroll
            for (int nt = 0; nt < 8; nt++) {
                const u32* vp_h = vb_h + nt * 8 * 32;
                const u32* vp_l = vb_l + nt * 8 * 32;
                u32 bh0 = vp_h[c0], bh1 = vp_h[c1];
                u32 bl0 = vp_l[c0], bl1 = vp_l[c1];
                mma_bf16(o[nt], ah0, ah1, ah2, ah3, bh0, bh1);
                mma_bf16(o[nt], al0, al1, al2, al3, bh0, bh1);
                mma_bf16(o[nt], ah0, ah1, ah2, ah3, bl0, bl1);
            }
        }
    }

    // ---- epilogue ----
    const float inv0 = __frcp_rn(l0);
    const float inv1 = __frcp_rn(l1);
    float* O0 = O + ((size_t)b * S_LEN + q0 + row0) * NQ + h * HD + 64 * kq;
    float* O8 = O0 + (size_t)8 * NQ;
#pragma unroll
    for (int nt = 0; nt < 8; nt++) {
        const int d = nt * 8 + 2 * tc;
        *(float2*)(O0 + d) = make_float2(o[nt][0] * inv0, o[nt][1] * inv0);
        *(float2*)(O8 + d) = make_float2(o[nt][2] * inv1, o[nt][3] * inv1);
    }
}

// ---------------------------------------------------------------------------
// Launch
// ---------------------------------------------------------------------------
extern "C" void kernel_launch(void* const* d_in, const int* in_sizes, int n_in,
                              void* d_out, int out_size)
{
    (void)in_sizes; (void)n_in; (void)out_size;
    const float* hidden = (const float*)d_in[0];
    const float* cosb   = (const float*)d_in[1];
    const float* sinb   = (const float*)d_in[2];
    // d_in[3] = attention_mask: analytic sliding-window mask used instead
    const float* Wq = (const float*)d_in[4];
    const float* Wk = (const float*)d_in[5];
    const float* Wv = (const float*)d_in[6];
    const float* Wo = (const float*)d_in[7];
    const float* qw = (const float*)d_in[8];
    const float* kw = (const float*)d_in[9];
    float* out = (float*)d_out;

    float *qraw, *kraw, *vraw, *qr, *kr;
    cudaGetSymbolAddress((void**)&qraw, g_Qraw);
    cudaGetSymbolAddress((void**)&kraw, g_Kraw);
    cudaGetSymbolAddress((void**)&vraw, g_Vraw);
    cudaGetSymbolAddress((void**)&qr, g_Qr);
    cudaGetSymbolAddress((void**)&kr, g_Kr);

    // Fused QKV projection (tf32 tensor cores)
    gemm_qkv_tf32<<<dim3(12, MROWS / 128), 256>>>(hidden, Wq, Wk, Wv, qraw, kraw, vraw);

    // RMSNorm + RoPE (Q pre-scaled by SCALING)
    normrope_kernel<<<MROWS, 256>>>(qraw, kraw, cosb, sinb, qw, kw, qr, kr);

    // Tensor-core windowed softcap attention (writes into qraw)
    cudaFuncSetAttribute(attn_mma_kernel, cudaFuncAttributeMaxDynamicSharedMemorySize,
                         ATT_SMEM_BYTES);
    attn_mma_kernel<<<dim3(S_LEN / QT, NH, B_DIM), 512, ATT_SMEM_BYTES>>>(qr, kr, vraw, qraw);

    // Output projection (tf32 tensor cores, 128x64 tiles)
    gemm_o_tf32<<<dim3(HID / 64, MROWS / 128), 256>>>(qraw, Wo, out, HID, NQ);
}